// round 1
// baseline (speedup 1.0000x reference)
#include <cuda_runtime.h>
#include <cuda_bf16.h>
#include <math.h>

// ---------------------------------------------------------------------------
// Problem constants: B=4, N=512, M=4096, D=256, H=8, HD=32
// ---------------------------------------------------------------------------
#define BB 4
#define NN 512
#define MM 4096
#define DD 256
#define HH 8
#define HD 32

#define AMR_ELEMS (BB * NN * DD)   // 524288
#define VIS_ELEMS (BB * MM * DD)   // 4194304

// Scratch (device globals: allocation-free per harness rules)
__device__ float g_amr_qk[AMR_ELEMS];
__device__ float g_amr_v [AMR_ELEMS];
__device__ float g_vis_qk[VIS_ELEMS];
__device__ float g_vis_v [VIS_ELEMS];
__device__ float g_amr_att[AMR_ELEMS];
__device__ float g_vis_att[VIS_ELEMS];
__device__ unsigned char g_mask[BB * NN];

// ---------------------------------------------------------------------------
// Mask expansion. The reference mask is jnp bool; the harness may serialize it
// as 1-byte bool or as a 4-byte type (int32/float32). Detect layout:
//   - byte layout: ~50% of bytes at idx%4==1 are nonzero (random 0/1 bools)
//   - 4-byte layout (int32 0/1 or float 0.0/1.0): byte at idx%4==1 is always 0
// Reading the first 2048 bytes is safe in every layout.
// For the 4-byte case, reading element i as int32 (nonzero test) covers both
// int32 and float32 encodings.
// ---------------------------------------------------------------------------
__global__ void mask_expand_kernel(const unsigned char* __restrict__ src) {
    __shared__ int flag;
    if (threadIdx.x == 0) flag = 0;
    __syncthreads();
    for (int i = threadIdx.x; i < 512; i += blockDim.x) {
        if (src[i * 4 + 1] != 0) atomicOr(&flag, 1);
    }
    __syncthreads();
    const int byte_layout = flag;
    for (int i = threadIdx.x; i < BB * NN; i += blockDim.x) {
        unsigned char v;
        if (byte_layout) {
            v = (src[i] != 0) ? 1 : 0;
        } else {
            v = (((const int*)src)[i] != 0) ? 1 : 0;
        }
        g_mask[i] = v;
    }
}

// ---------------------------------------------------------------------------
// GEMM: C[R,256] = A[R,256] @ W[256,256]  (+ bias) (* mul elementwise)
// Tiles: 64x64, BK=32, 256 threads, 4x4 per thread. R and 256 divisible by 64.
// grid = (R/64, 4)
// ---------------------------------------------------------------------------
__global__ __launch_bounds__(256)
void gemm_d256_kernel(const float* __restrict__ A, const float* __restrict__ W,
                      float* __restrict__ C,
                      const float* __restrict__ bias,
                      const float* __restrict__ mul) {
    __shared__ float As[32][68];   // [k][m], padded (16B-aligned rows)
    __shared__ float Ws[32][64];   // [k][n]

    const int tid = threadIdx.x;
    const int ty = tid >> 4;       // 0..15 -> 4 rows each
    const int tx = tid & 15;       // 0..15 -> 4 cols each
    const int row0 = blockIdx.x * 64;
    const int col0 = blockIdx.y * 64;

    float acc[4][4] = {};

    for (int kt = 0; kt < 256; kt += 32) {
        __syncthreads();
#pragma unroll
        for (int l = 0; l < 2; l++) {
            int idx = tid + l * 256;       // 0..511
            int r  = idx >> 3;             // 0..63
            int kc = idx & 7;              // 0..7 (float4 along k)
            float4 a = *(const float4*)&A[(size_t)(row0 + r) * 256 + kt + kc * 4];
            As[kc * 4 + 0][r] = a.x;
            As[kc * 4 + 1][r] = a.y;
            As[kc * 4 + 2][r] = a.z;
            As[kc * 4 + 3][r] = a.w;
            int kr = idx >> 4;             // 0..31
            int nc = idx & 15;             // 0..15
            *(float4*)&Ws[kr][nc * 4] =
                *(const float4*)&W[(size_t)(kt + kr) * 256 + col0 + nc * 4];
        }
        __syncthreads();
#pragma unroll
        for (int k = 0; k < 32; k++) {
            float4 a4 = *(const float4*)&As[k][ty * 4];
            float4 b4 = *(const float4*)&Ws[k][tx * 4];
            float av[4] = {a4.x, a4.y, a4.z, a4.w};
            float bv[4] = {b4.x, b4.y, b4.z, b4.w};
#pragma unroll
            for (int i = 0; i < 4; i++)
#pragma unroll
                for (int j = 0; j < 4; j++)
                    acc[i][j] += av[i] * bv[j];
        }
    }

#pragma unroll
    for (int i = 0; i < 4; i++) {
        int r = row0 + ty * 4 + i;
        int c = col0 + tx * 4;
        float4 v = make_float4(acc[i][0], acc[i][1], acc[i][2], acc[i][3]);
        if (bias) {
            v.x += bias[c + 0]; v.y += bias[c + 1];
            v.z += bias[c + 2]; v.w += bias[c + 3];
        }
        if (mul) {
            float4 m = *(const float4*)&mul[(size_t)r * 256 + c];
            v.x *= m.x; v.y *= m.y; v.z *= m.z; v.w *= m.w;
        }
        *(float4*)&C[(size_t)r * 256 + c] = v;
    }
}

// ---------------------------------------------------------------------------
// Fused flash attention, fp32, one head per blockIdx.y (b*8+h).
// Q:[B,Lq,256] K,V:[B,Lk,256] (head h = columns h*32..h*32+31), O:[B,Lq,256].
// Block: 32 queries, loop keys in tiles of 64. 128 threads:
//   ty=tid/16 (8 groups x 4 q-rows), tx=tid%16 (16 groups x 4 k-cols / 2 v-cols)
// Online softmax with width-16 shuffle reductions (rows live in 16-lane halves).
// mask (nullable): per-batch byte mask over keys; masked key -> score = -1e30.
// ---------------------------------------------------------------------------
__global__ __launch_bounds__(128)
void attn_kernel(const float* __restrict__ Q, const float* __restrict__ K,
                 const float* __restrict__ V, float* __restrict__ O,
                 const unsigned char* __restrict__ mask,
                 int Lq, int Lk) {
    const int bh = blockIdx.y;
    const int b = bh >> 3;
    const int h = bh & 7;
    const int q0 = blockIdx.x * 32;
    const int tid = threadIdx.x;
    const int ty = tid >> 4;   // 0..7
    const int tx = tid & 15;   // 0..15
    const float scale = 0.17677669529663687f;  // 32^-0.5

    __shared__ float Qt[32][36];   // [c][q]
    __shared__ float Kt[32][68];   // [c][k]
    __shared__ float Vs[64][36];   // [k][c]
    __shared__ float Pt[64][36];   // [k][q]

    const float* Qb = Q + (size_t)b * Lq * 256 + h * 32;
    const float* Kb = K + (size_t)b * Lk * 256 + h * 32;
    const float* Vb = V + (size_t)b * Lk * 256 + h * 32;
    const unsigned char* mb = mask ? (mask + (size_t)b * Lk) : (const unsigned char*)0;

    // Load Q tile transposed: 32 rows x 32 dims = 256 float4
#pragma unroll
    for (int l = 0; l < 2; l++) {
        int idx = tid + l * 128;
        int r = idx >> 3, c4 = idx & 7;
        float4 v = *(const float4*)&Qb[(size_t)(q0 + r) * 256 + c4 * 4];
        Qt[c4 * 4 + 0][r] = v.x;
        Qt[c4 * 4 + 1][r] = v.y;
        Qt[c4 * 4 + 2][r] = v.z;
        Qt[c4 * 4 + 3][r] = v.w;
    }

    float accO[4][2] = {};
    float rmax[4], rsum[4];
#pragma unroll
    for (int i = 0; i < 4; i++) { rmax[i] = -1e30f; rsum[i] = 0.0f; }

    for (int m0 = 0; m0 < Lk; m0 += 64) {
        __syncthreads();   // protect Kt/Vs/Pt from prior iteration's readers
        // Load K (transposed) and V tiles: 64 keys x 32 dims each
#pragma unroll
        for (int l = 0; l < 4; l++) {
            int idx = tid + l * 128;
            int kk = idx >> 3, c4 = idx & 7;
            float4 kv = *(const float4*)&Kb[(size_t)(m0 + kk) * 256 + c4 * 4];
            Kt[c4 * 4 + 0][kk] = kv.x;
            Kt[c4 * 4 + 1][kk] = kv.y;
            Kt[c4 * 4 + 2][kk] = kv.z;
            Kt[c4 * 4 + 3][kk] = kv.w;
            *(float4*)&Vs[kk][c4 * 4] =
                *(const float4*)&Vb[(size_t)(m0 + kk) * 256 + c4 * 4];
        }
        __syncthreads();

        // S[4q][4k] = (Q . K) * scale
        float s[4][4] = {};
#pragma unroll
        for (int c = 0; c < 32; c++) {
            float4 a4 = *(const float4*)&Qt[c][ty * 4];
            float4 k4 = *(const float4*)&Kt[c][tx * 4];
            float av[4] = {a4.x, a4.y, a4.z, a4.w};
            float kv[4] = {k4.x, k4.y, k4.z, k4.w};
#pragma unroll
            for (int i = 0; i < 4; i++)
#pragma unroll
                for (int j = 0; j < 4; j++)
                    s[i][j] += av[i] * kv[j];
        }
#pragma unroll
        for (int i = 0; i < 4; i++)
#pragma unroll
            for (int j = 0; j < 4; j++)
                s[i][j] *= scale;

        if (mb) {
#pragma unroll
            for (int j = 0; j < 4; j++) {
                if (mb[m0 + tx * 4 + j]) {
                    s[0][j] = -1e30f; s[1][j] = -1e30f;
                    s[2][j] = -1e30f; s[3][j] = -1e30f;
                }
            }
        }

        // Online softmax per query row (rows span 16 lanes: same-ty group)
#pragma unroll
        for (int i = 0; i < 4; i++) {
            float mloc = fmaxf(fmaxf(s[i][0], s[i][1]), fmaxf(s[i][2], s[i][3]));
#pragma unroll
            for (int off = 8; off >= 1; off >>= 1)
                mloc = fmaxf(mloc, __shfl_xor_sync(0xffffffffu, mloc, off));
            float nm = fmaxf(rmax[i], mloc);
            float corr = __expf(rmax[i] - nm);
            rmax[i] = nm;
            float ls = 0.0f;
#pragma unroll
            for (int j = 0; j < 4; j++) {
                s[i][j] = __expf(s[i][j] - nm);
                ls += s[i][j];
            }
#pragma unroll
            for (int off = 8; off >= 1; off >>= 1)
                ls += __shfl_xor_sync(0xffffffffu, ls, off);
            rsum[i] = rsum[i] * corr + ls;
            accO[i][0] *= corr;
            accO[i][1] *= corr;
        }

        // Write P transposed: Pt[k][q]
#pragma unroll
        for (int j = 0; j < 4; j++) {
            float4 pv = make_float4(s[0][j], s[1][j], s[2][j], s[3][j]);
            *(float4*)&Pt[tx * 4 + j][ty * 4] = pv;
        }
        __syncthreads();

        // O += P @ V  (thread owns 4 q-rows x 2 v-cols {2tx, 2tx+1})
#pragma unroll 8
        for (int k = 0; k < 64; k++) {
            float4 p = *(const float4*)&Pt[k][ty * 4];
            float v0 = Vs[k][tx * 2 + 0];
            float v1 = Vs[k][tx * 2 + 1];
            accO[0][0] += p.x * v0;  accO[0][1] += p.x * v1;
            accO[1][0] += p.y * v0;  accO[1][1] += p.y * v1;
            accO[2][0] += p.z * v0;  accO[2][1] += p.z * v1;
            accO[3][0] += p.w * v0;  accO[3][1] += p.w * v1;
        }
    }

    float* Ob = O + (size_t)b * Lq * 256 + h * 32;
#pragma unroll
    for (int i = 0; i < 4; i++) {
        float inv = 1.0f / rsum[i];
        float2 o = make_float2(accO[i][0] * inv, accO[i][1] * inv);
        *(float2*)&Ob[(size_t)(q0 + ty * 4 + i) * 256 + tx * 2] = o;
    }
}

// ---------------------------------------------------------------------------
// kernel_launch: graph-capturable, allocation-free.
// Input order (metadata): amr_feats, amr_pad_mask, visual_feats, W_amr_qk,
//   W_amr_v, W_vis_qk, W_vis_v, W_amr_out, b_amr_out, W_vis_out, b_vis_out.
// Output: [amr_out (B*N*D) | vis_out (B*M*D)] concatenated, fp32.
// ---------------------------------------------------------------------------
extern "C" void kernel_launch(void* const* d_in, const int* in_sizes, int n_in,
                              void* d_out, int out_size) {
    (void)in_sizes; (void)n_in; (void)out_size;

    const float* amr       = (const float*)d_in[0];
    const unsigned char* m = (const unsigned char*)d_in[1];
    const float* vis       = (const float*)d_in[2];
    const float* W_amr_qk  = (const float*)d_in[3];
    const float* W_amr_v   = (const float*)d_in[4];
    const float* W_vis_qk  = (const float*)d_in[5];
    const float* W_vis_v   = (const float*)d_in[6];
    const float* W_amr_out = (const float*)d_in[7];
    const float* b_amr     = (const float*)d_in[8];
    const float* W_vis_out = (const float*)d_in[9];
    const float* b_vis     = (const float*)d_in[10];
    float* out = (float*)d_out;

    float *amr_qk, *amr_v, *vis_qk, *vis_v, *amr_att, *vis_att;
    unsigned char* maskexp;
    cudaGetSymbolAddress((void**)&amr_qk,  g_amr_qk);
    cudaGetSymbolAddress((void**)&amr_v,   g_amr_v);
    cudaGetSymbolAddress((void**)&vis_qk,  g_vis_qk);
    cudaGetSymbolAddress((void**)&vis_v,   g_vis_v);
    cudaGetSymbolAddress((void**)&amr_att, g_amr_att);
    cudaGetSymbolAddress((void**)&vis_att, g_vis_att);
    cudaGetSymbolAddress((void**)&maskexp, g_mask);

    // Mask decode (dtype-robust)
    mask_expand_kernel<<<1, 256>>>(m);

    // Input projections
    gemm_d256_kernel<<<dim3(BB * NN / 64, 4), 256>>>(amr, W_amr_qk, amr_qk, 0, 0);
    gemm_d256_kernel<<<dim3(BB * NN / 64, 4), 256>>>(amr, W_amr_v,  amr_v,  0, 0);
    gemm_d256_kernel<<<dim3(BB * MM / 64, 4), 256>>>(vis, W_vis_qk, vis_qk, 0, 0);
    gemm_d256_kernel<<<dim3(BB * MM / 64, 4), 256>>>(vis, W_vis_v,  vis_v,  0, 0);

    // amr -> visual (no mask): Q=amr_qk, K=vis_qk, V=vis_v
    attn_kernel<<<dim3(NN / 32, BB * HH), 128>>>(
        amr_qk, vis_qk, vis_v, amr_att, (const unsigned char*)0, NN, MM);

    // visual -> amr (masked keys = amr positions): Q=vis_qk, K=amr_qk, V=amr_v
    attn_kernel<<<dim3(MM / 32, BB * HH), 128>>>(
        vis_qk, amr_qk, amr_v, vis_att, maskexp, MM, NN);

    // Output projections fused with bias add and elementwise input multiply
    gemm_d256_kernel<<<dim3(BB * NN / 64, 4), 256>>>(
        amr_att, W_amr_out, out, b_amr, amr);
    gemm_d256_kernel<<<dim3(BB * MM / 64, 4), 256>>>(
        vis_att, W_vis_out, out + AMR_ELEMS, b_vis, vis);
}

// round 2
// speedup vs baseline: 1.0012x; 1.0012x over previous
#include <cuda_runtime.h>
#include <cuda_bf16.h>
#include <math.h>

// ---------------------------------------------------------------------------
// Problem constants: B=4, N=512, M=4096, D=256, H=8, HD=32
// ---------------------------------------------------------------------------
#define BB 4
#define NN 512
#define MM 4096
#define DD 256
#define HH 8
#define HD 32

#define AMR_ELEMS (BB * NN * DD)   // 524288
#define VIS_ELEMS (BB * MM * DD)   // 4194304

// Scratch (device globals: allocation-free per harness rules)
__device__ float g_amr_qk[AMR_ELEMS];
__device__ float g_amr_v [AMR_ELEMS];
__device__ float g_vis_qk[VIS_ELEMS];
__device__ float g_vis_v [VIS_ELEMS];
__device__ float g_amr_att[AMR_ELEMS];
__device__ float g_vis_att[VIS_ELEMS];
__device__ unsigned char g_mask[BB * NN];

// ---------------------------------------------------------------------------
// Mask expansion. The reference mask is jnp bool; the harness may serialize it
// as 1-byte bool or as a 4-byte type (int32/float32). Detect layout:
//   - byte layout: ~50% of bytes at idx%4==1 are nonzero (random 0/1 bools)
//   - 4-byte layout (int32 0/1 or float 0.0/1.0): byte at idx%4==1 is always 0
// Reading the first 2048 bytes is safe in every layout.
// For the 4-byte case, reading element i as int32 (nonzero test) covers both
// int32 and float32 encodings.
// ---------------------------------------------------------------------------
__global__ void mask_expand_kernel(const unsigned char* __restrict__ src) {
    __shared__ int flag;
    if (threadIdx.x == 0) flag = 0;
    __syncthreads();
    for (int i = threadIdx.x; i < 512; i += blockDim.x) {
        if (src[i * 4 + 1] != 0) atomicOr(&flag, 1);
    }
    __syncthreads();
    const int byte_layout = flag;
    for (int i = threadIdx.x; i < BB * NN; i += blockDim.x) {
        unsigned char v;
        if (byte_layout) {
            v = (src[i] != 0) ? 1 : 0;
        } else {
            v = (((const int*)src)[i] != 0) ? 1 : 0;
        }
        g_mask[i] = v;
    }
}

// ---------------------------------------------------------------------------
// GEMM: C[R,256] = A[R,256] @ W[256,256]  (+ bias) (* mul elementwise)
// Tiles: 64x64, BK=32, 256 threads, 4x4 per thread. R and 256 divisible by 64.
// grid = (R/64, 4)
// ---------------------------------------------------------------------------
__global__ __launch_bounds__(256)
void gemm_d256_kernel(const float* __restrict__ A, const float* __restrict__ W,
                      float* __restrict__ C,
                      const float* __restrict__ bias,
                      const float* __restrict__ mul) {
    __shared__ float As[32][68];   // [k][m], padded (16B-aligned rows)
    __shared__ float Ws[32][64];   // [k][n]

    const int tid = threadIdx.x;
    const int ty = tid >> 4;       // 0..15 -> 4 rows each
    const int tx = tid & 15;       // 0..15 -> 4 cols each
    const int row0 = blockIdx.x * 64;
    const int col0 = blockIdx.y * 64;

    float acc[4][4] = {};

    for (int kt = 0; kt < 256; kt += 32) {
        __syncthreads();
#pragma unroll
        for (int l = 0; l < 2; l++) {
            int idx = tid + l * 256;       // 0..511
            int r  = idx >> 3;             // 0..63
            int kc = idx & 7;              // 0..7 (float4 along k)
            float4 a = *(const float4*)&A[(size_t)(row0 + r) * 256 + kt + kc * 4];
            As[kc * 4 + 0][r] = a.x;
            As[kc * 4 + 1][r] = a.y;
            As[kc * 4 + 2][r] = a.z;
            As[kc * 4 + 3][r] = a.w;
            int kr = idx >> 4;             // 0..31
            int nc = idx & 15;             // 0..15
            *(float4*)&Ws[kr][nc * 4] =
                *(const float4*)&W[(size_t)(kt + kr) * 256 + col0 + nc * 4];
        }
        __syncthreads();
#pragma unroll
        for (int k = 0; k < 32; k++) {
            float4 a4 = *(const float4*)&As[k][ty * 4];
            float4 b4 = *(const float4*)&Ws[k][tx * 4];
            float av[4] = {a4.x, a4.y, a4.z, a4.w};
            float bv[4] = {b4.x, b4.y, b4.z, b4.w};
#pragma unroll
            for (int i = 0; i < 4; i++)
#pragma unroll
                for (int j = 0; j < 4; j++)
                    acc[i][j] += av[i] * bv[j];
        }
    }

#pragma unroll
    for (int i = 0; i < 4; i++) {
        int r = row0 + ty * 4 + i;
        int c = col0 + tx * 4;
        float4 v = make_float4(acc[i][0], acc[i][1], acc[i][2], acc[i][3]);
        if (bias) {
            v.x += bias[c + 0]; v.y += bias[c + 1];
            v.z += bias[c + 2]; v.w += bias[c + 3];
        }
        if (mul) {
            float4 m = *(const float4*)&mul[(size_t)r * 256 + c];
            v.x *= m.x; v.y *= m.y; v.z *= m.z; v.w *= m.w;
        }
        *(float4*)&C[(size_t)r * 256 + c] = v;
    }
}

// ---------------------------------------------------------------------------
// Fused flash attention, fp32, one head per blockIdx.y (b*8+h).
// Q:[B,Lq,256] K,V:[B,Lk,256] (head h = columns h*32..h*32+31), O:[B,Lq,256].
// Block: 32 queries, loop keys in tiles of 64. 128 threads:
//   ty=tid/16 (8 groups x 4 q-rows), tx=tid%16 (16 groups x 4 k-cols / 2 v-cols)
// Online softmax with width-16 shuffle reductions (rows live in 16-lane halves).
// mask (nullable): per-batch byte mask over keys; masked key -> score = -1e30.
// ---------------------------------------------------------------------------
__global__ __launch_bounds__(128)
void attn_kernel(const float* __restrict__ Q, const float* __restrict__ K,
                 const float* __restrict__ V, float* __restrict__ O,
                 const unsigned char* __restrict__ mask,
                 int Lq, int Lk) {
    const int bh = blockIdx.y;
    const int b = bh >> 3;
    const int h = bh & 7;
    const int q0 = blockIdx.x * 32;
    const int tid = threadIdx.x;
    const int ty = tid >> 4;   // 0..7
    const int tx = tid & 15;   // 0..15
    const float scale = 0.17677669529663687f;  // 32^-0.5

    __shared__ float Qt[32][36];   // [c][q]
    __shared__ float Kt[32][68];   // [c][k]
    __shared__ float Vs[64][36];   // [k][c]
    __shared__ float Pt[64][36];   // [k][q]

    const float* Qb = Q + (size_t)b * Lq * 256 + h * 32;
    const float* Kb = K + (size_t)b * Lk * 256 + h * 32;
    const float* Vb = V + (size_t)b * Lk * 256 + h * 32;
    const unsigned char* mb = mask ? (mask + (size_t)b * Lk) : (const unsigned char*)0;

    // Load Q tile transposed: 32 rows x 32 dims = 256 float4
#pragma unroll
    for (int l = 0; l < 2; l++) {
        int idx = tid + l * 128;
        int r = idx >> 3, c4 = idx & 7;
        float4 v = *(const float4*)&Qb[(size_t)(q0 + r) * 256 + c4 * 4];
        Qt[c4 * 4 + 0][r] = v.x;
        Qt[c4 * 4 + 1][r] = v.y;
        Qt[c4 * 4 + 2][r] = v.z;
        Qt[c4 * 4 + 3][r] = v.w;
    }

    float accO[4][2] = {};
    float rmax[4], rsum[4];
#pragma unroll
    for (int i = 0; i < 4; i++) { rmax[i] = -1e30f; rsum[i] = 0.0f; }

    for (int m0 = 0; m0 < Lk; m0 += 64) {
        __syncthreads();   // protect Kt/Vs/Pt from prior iteration's readers
        // Load K (transposed) and V tiles: 64 keys x 32 dims each
#pragma unroll
        for (int l = 0; l < 4; l++) {
            int idx = tid + l * 128;
            int kk = idx >> 3, c4 = idx & 7;
            float4 kv = *(const float4*)&Kb[(size_t)(m0 + kk) * 256 + c4 * 4];
            Kt[c4 * 4 + 0][kk] = kv.x;
            Kt[c4 * 4 + 1][kk] = kv.y;
            Kt[c4 * 4 + 2][kk] = kv.z;
            Kt[c4 * 4 + 3][kk] = kv.w;
            *(float4*)&Vs[kk][c4 * 4] =
                *(const float4*)&Vb[(size_t)(m0 + kk) * 256 + c4 * 4];
        }
        __syncthreads();

        // S[4q][4k] = (Q . K) * scale
        float s[4][4] = {};
#pragma unroll
        for (int c = 0; c < 32; c++) {
            float4 a4 = *(const float4*)&Qt[c][ty * 4];
            float4 k4 = *(const float4*)&Kt[c][tx * 4];
            float av[4] = {a4.x, a4.y, a4.z, a4.w};
            float kv[4] = {k4.x, k4.y, k4.z, k4.w};
#pragma unroll
            for (int i = 0; i < 4; i++)
#pragma unroll
                for (int j = 0; j < 4; j++)
                    s[i][j] += av[i] * kv[j];
        }
#pragma unroll
        for (int i = 0; i < 4; i++)
#pragma unroll
            for (int j = 0; j < 4; j++)
                s[i][j] *= scale;

        if (mb) {
#pragma unroll
            for (int j = 0; j < 4; j++) {
                if (mb[m0 + tx * 4 + j]) {
                    s[0][j] = -1e30f; s[1][j] = -1e30f;
                    s[2][j] = -1e30f; s[3][j] = -1e30f;
                }
            }
        }

        // Online softmax per query row (rows span 16 lanes: same-ty group)
#pragma unroll
        for (int i = 0; i < 4; i++) {
            float mloc = fmaxf(fmaxf(s[i][0], s[i][1]), fmaxf(s[i][2], s[i][3]));
#pragma unroll
            for (int off = 8; off >= 1; off >>= 1)
                mloc = fmaxf(mloc, __shfl_xor_sync(0xffffffffu, mloc, off));
            float nm = fmaxf(rmax[i], mloc);
            float corr = __expf(rmax[i] - nm);
            rmax[i] = nm;
            float ls = 0.0f;
#pragma unroll
            for (int j = 0; j < 4; j++) {
                s[i][j] = __expf(s[i][j] - nm);
                ls += s[i][j];
            }
#pragma unroll
            for (int off = 8; off >= 1; off >>= 1)
                ls += __shfl_xor_sync(0xffffffffu, ls, off);
            rsum[i] = rsum[i] * corr + ls;
            accO[i][0] *= corr;
            accO[i][1] *= corr;
        }

        // Write P transposed: Pt[k][q]
#pragma unroll
        for (int j = 0; j < 4; j++) {
            float4 pv = make_float4(s[0][j], s[1][j], s[2][j], s[3][j]);
            *(float4*)&Pt[tx * 4 + j][ty * 4] = pv;
        }
        __syncthreads();

        // O += P @ V  (thread owns 4 q-rows x 2 v-cols {2tx, 2tx+1})
#pragma unroll 8
        for (int k = 0; k < 64; k++) {
            float4 p = *(const float4*)&Pt[k][ty * 4];
            float v0 = Vs[k][tx * 2 + 0];
            float v1 = Vs[k][tx * 2 + 1];
            accO[0][0] += p.x * v0;  accO[0][1] += p.x * v1;
            accO[1][0] += p.y * v0;  accO[1][1] += p.y * v1;
            accO[2][0] += p.z * v0;  accO[2][1] += p.z * v1;
            accO[3][0] += p.w * v0;  accO[3][1] += p.w * v1;
        }
    }

    float* Ob = O + (size_t)b * Lq * 256 + h * 32;
#pragma unroll
    for (int i = 0; i < 4; i++) {
        float inv = 1.0f / rsum[i];
        float2 o = make_float2(accO[i][0] * inv, accO[i][1] * inv);
        *(float2*)&Ob[(size_t)(q0 + ty * 4 + i) * 256 + tx * 2] = o;
    }
}

// ---------------------------------------------------------------------------
// kernel_launch: graph-capturable, allocation-free.
// Input order (metadata): amr_feats, amr_pad_mask, visual_feats, W_amr_qk,
//   W_amr_v, W_vis_qk, W_vis_v, W_amr_out, b_amr_out, W_vis_out, b_vis_out.
// Output: [amr_out (B*N*D) | vis_out (B*M*D)] concatenated, fp32.
// ---------------------------------------------------------------------------
extern "C" void kernel_launch(void* const* d_in, const int* in_sizes, int n_in,
                              void* d_out, int out_size) {
    (void)in_sizes; (void)n_in; (void)out_size;

    const float* amr       = (const float*)d_in[0];
    const unsigned char* m = (const unsigned char*)d_in[1];
    const float* vis       = (const float*)d_in[2];
    const float* W_amr_qk  = (const float*)d_in[3];
    const float* W_amr_v   = (const float*)d_in[4];
    const float* W_vis_qk  = (const float*)d_in[5];
    const float* W_vis_v   = (const float*)d_in[6];
    const float* W_amr_out = (const float*)d_in[7];
    const float* b_amr     = (const float*)d_in[8];
    const float* W_vis_out = (const float*)d_in[9];
    const float* b_vis     = (const float*)d_in[10];
    float* out = (float*)d_out;

    float *amr_qk, *amr_v, *vis_qk, *vis_v, *amr_att, *vis_att;
    unsigned char* maskexp;
    cudaGetSymbolAddress((void**)&amr_qk,  g_amr_qk);
    cudaGetSymbolAddress((void**)&amr_v,   g_amr_v);
    cudaGetSymbolAddress((void**)&vis_qk,  g_vis_qk);
    cudaGetSymbolAddress((void**)&vis_v,   g_vis_v);
    cudaGetSymbolAddress((void**)&amr_att, g_amr_att);
    cudaGetSymbolAddress((void**)&vis_att, g_vis_att);
    cudaGetSymbolAddress((void**)&maskexp, g_mask);

    // Mask decode (dtype-robust)
    mask_expand_kernel<<<1, 256>>>(m);

    // Input projections
    gemm_d256_kernel<<<dim3(BB * NN / 64, 4), 256>>>(amr, W_amr_qk, amr_qk, 0, 0);
    gemm_d256_kernel<<<dim3(BB * NN / 64, 4), 256>>>(amr, W_amr_v,  amr_v,  0, 0);
    gemm_d256_kernel<<<dim3(BB * MM / 64, 4), 256>>>(vis, W_vis_qk, vis_qk, 0, 0);
    gemm_d256_kernel<<<dim3(BB * MM / 64, 4), 256>>>(vis, W_vis_v,  vis_v,  0, 0);

    // amr -> visual (no mask): Q=amr_qk, K=vis_qk, V=vis_v
    attn_kernel<<<dim3(NN / 32, BB * HH), 128>>>(
        amr_qk, vis_qk, vis_v, amr_att, (const unsigned char*)0, NN, MM);

    // visual -> amr (masked keys = amr positions): Q=vis_qk, K=amr_qk, V=amr_v
    attn_kernel<<<dim3(MM / 32, BB * HH), 128>>>(
        vis_qk, amr_qk, amr_v, vis_att, maskexp, MM, NN);

    // Output projections fused with bias add and elementwise input multiply
    gemm_d256_kernel<<<dim3(BB * NN / 64, 4), 256>>>(
        amr_att, W_amr_out, out, b_amr, amr);
    gemm_d256_kernel<<<dim3(BB * MM / 64, 4), 256>>>(
        vis_att, W_vis_out, out + AMR_ELEMS, b_vis, vis);
}